// round 14
// baseline (speedup 1.0000x reference)
#include <cuda_runtime.h>
#include <cuda_fp16.h>
#include <cstdint>

// Problem constants
#define BB 2
#define SS 2048
#define DD 1024
#define HH 16
#define DK 64
#define MROWS 4096
#define MD (MROWS * DD)
#define NN (DD * DD)
#define GG (BB * SS * SS)

// Scratch (alloc-free rule: __device__ globals), all fp16
__device__ __half g_in_h[3 * MD];   // query,key,value converted
__device__ __half g_w_h[4 * NN];    // Wq,Wk,Wv,Wo converted
__device__ __half g_qkv[3 * MD];    // projected Q,K,V
__device__ __half g_o_h[MD];        // attention output
__device__ __half g_gh[GG];         // group_prob fp16

// ---------------------------------------------------------------------------
// Helpers
// ---------------------------------------------------------------------------
__device__ __forceinline__ uint32_t smem_to_u32(const void* p) {
    uint32_t a;
    asm("{ .reg .u64 t; cvta.to.shared.u64 t, %1; cvt.u32.u64 %0, t; }" : "=r"(a) : "l"(p));
    return a;
}
__device__ __forceinline__ uint32_t packh2(float x, float y) {
    __half2 h = __floats2half2_rn(x, y);
    return *(uint32_t*)&h;
}
__device__ __forceinline__ uint32_t h2ex2(uint32_t x) {
    uint32_t r; asm("ex2.approx.f16x2 %0, %1;" : "=r"(r) : "r"(x)); return r;
}
__device__ __forceinline__ uint32_t h2mul(uint32_t a, uint32_t b) {
    uint32_t r; asm("mul.f16x2 %0, %1, %2;" : "=r"(r) : "r"(a), "r"(b)); return r;
}
#define CP_ASYNC16(dst, src) \
    asm volatile("cp.async.cg.shared.global [%0], [%1], 16;" :: "r"((uint32_t)(dst)), "l"(src))
#define CP_COMMIT() asm volatile("cp.async.commit_group;" ::: "memory")
#define CP_WAIT2()  asm volatile("cp.async.wait_group 2;" ::: "memory")
#define CP_WAIT1()  asm volatile("cp.async.wait_group 1;" ::: "memory")
#define CP_WAIT0()  asm volatile("cp.async.wait_group 0;" ::: "memory")

__device__ __forceinline__ void mma_f16(float* c, const uint32_t* a, const uint32_t* b) {
    asm volatile(
        "mma.sync.aligned.m16n8k16.row.col.f32.f16.f16.f32 "
        "{%0,%1,%2,%3}, {%4,%5,%6,%7}, {%8,%9}, {%0,%1,%2,%3};"
        : "+f"(c[0]), "+f"(c[1]), "+f"(c[2]), "+f"(c[3])
        : "r"(a[0]), "r"(a[1]), "r"(a[2]), "r"(a[3]), "r"(b[0]), "r"(b[1]));
}
__device__ __forceinline__ void ldsm4(uint32_t* r, uint32_t a) {
    asm volatile("ldmatrix.sync.aligned.m8n8.x4.shared.b16 {%0,%1,%2,%3}, [%4];"
        : "=r"(r[0]), "=r"(r[1]), "=r"(r[2]), "=r"(r[3]) : "r"(a));
}
__device__ __forceinline__ void ldsm4t(uint32_t* r, uint32_t a) {
    asm volatile("ldmatrix.sync.aligned.m8n8.x4.trans.shared.b16 {%0,%1,%2,%3}, [%4];"
        : "=r"(r[0]), "=r"(r[1]), "=r"(r[2]), "=r"(r[3]) : "r"(a));
}

// ---------------------------------------------------------------------------
// Batched fp32 -> fp16 convert
// ---------------------------------------------------------------------------
struct CvtArgs { const float* src[4]; __half* dst[4]; };

__global__ __launch_bounds__(256) void cvt_half(CvtArgs args) {
    const float* in = args.src[blockIdx.z];
    __half* out = args.dst[blockIdx.z];
    int i = (blockIdx.x * 256 + threadIdx.x) * 8;
    float4 v0 = *(const float4*)(in + i);
    float4 v1 = *(const float4*)(in + i + 4);
    uint4 o;
    o.x = packh2(v0.x, v0.y);
    o.y = packh2(v0.z, v0.w);
    o.z = packh2(v1.x, v1.y);
    o.w = packh2(v1.z, v1.w);
    *(uint4*)(out + i) = o;
}

// ---------------------------------------------------------------------------
// fp16 GEMM body (unchanged): C = A * W^T + bias, ldmatrix frags.
// ---------------------------------------------------------------------------
#define G_NS 4
#define G_ROWB 80
#define G_TILE_B (128 * G_ROWB)
#define G_STAGE_B (2 * G_TILE_B)
#define G_SMEM_TOTAL (G_NS * G_STAGE_B)

template <typename OutT>
__device__ __forceinline__ void gemm_body(
    const __half* __restrict__ A, const __half* __restrict__ W,
    const float* __restrict__ bias, OutT* __restrict__ C, char* smem)
{
    const uint32_t sb = smem_to_u32(smem);
    const int t = threadIdx.x;
    const int wid = t >> 5, lane = t & 31;
    const int g = lane >> 2, tig = lane & 3;
    const int wm = wid >> 2, wn = wid & 3;
    const int m0 = blockIdx.y * 128, n0 = blockIdx.x * 128;
    const int K = DD;

    const __half* Ab = A + (size_t)m0 * K;
    const __half* Wb = W + (size_t)n0 * K;

    const int lrow = t >> 1;
    const int cp = (t & 1) * 2;

    auto load_stage = [&](int s, int kt) {
        uint32_t sa = sb + s * G_STAGE_B + lrow * G_ROWB + cp * 16;
        uint32_t sw = sa + G_TILE_B;
        const __half* ga = Ab + (size_t)lrow * K + kt * 32 + cp * 8;
        const __half* gw = Wb + (size_t)lrow * K + kt * 32 + cp * 8;
        CP_ASYNC16(sa, ga);
        CP_ASYNC16(sa + 16, ga + 8);
        CP_ASYNC16(sw, gw);
        CP_ASYNC16(sw + 16, gw + 8);
    };

    const uint32_t aoff = (uint32_t)((wm * 64 + (lane & 15)) * G_ROWB + (lane >> 4) * 16);
    const uint32_t boff = (uint32_t)((wn * 32 + (lane & 7) + (lane >> 4) * 8) * G_ROWB
                                     + ((lane >> 3) & 1) * 16);

    float acc[4][4][4];
#pragma unroll
    for (int i = 0; i < 4; i++)
#pragma unroll
        for (int j = 0; j < 4; j++)
#pragma unroll
            for (int k = 0; k < 4; k++) acc[i][j][k] = 0.0f;

    const int NT = K / 32;
    for (int s = 0; s < G_NS - 1; s++) { load_stage(s, s); CP_COMMIT(); }

    for (int kt = 0; kt < NT; kt++) {
        CP_WAIT2();
        __syncthreads();
        {
            const uint32_t sA = sb + (kt & 3) * G_STAGE_B;
            const uint32_t sW = sA + G_TILE_B;
#pragma unroll
            for (int ks = 0; ks < 2; ks++) {
                uint32_t a[4][4], b[4][2];
#pragma unroll
                for (int mf = 0; mf < 4; mf++)
                    ldsm4(a[mf], sA + aoff + mf * (16 * G_ROWB) + ks * 32);
#pragma unroll
                for (int np = 0; np < 2; np++) {
                    uint32_t t4[4];
                    ldsm4(t4, sW + boff + np * (16 * G_ROWB) + ks * 32);
                    b[2 * np][0] = t4[0]; b[2 * np][1] = t4[1];
                    b[2 * np + 1][0] = t4[2]; b[2 * np + 1][1] = t4[3];
                }
#pragma unroll
                for (int mf = 0; mf < 4; mf++)
#pragma unroll
                    for (int nf = 0; nf < 4; nf++)
                        mma_f16(acc[mf][nf], a[mf], b[nf]);
            }
        }
        __syncthreads();
        const int nx = kt + G_NS - 1;
        if (nx < NT) { load_stage(nx & 3, nx); CP_COMMIT(); }
    }

#pragma unroll
    for (int mf = 0; mf < 4; mf++) {
        const int r = m0 + wm * 64 + mf * 16 + g;
#pragma unroll
        for (int nf = 0; nf < 4; nf++) {
            const int c = n0 + wn * 32 + nf * 8 + tig * 2;
            const float b0 = bias[c], b1 = bias[c + 1];
            if constexpr (sizeof(OutT) == 2) {
                __half2* p0 = (__half2*)&C[(size_t)r * DD + c];
                __half2* p1 = (__half2*)&C[(size_t)(r + 8) * DD + c];
                *p0 = __floats2half2_rn(acc[mf][nf][0] + b0, acc[mf][nf][1] + b1);
                *p1 = __floats2half2_rn(acc[mf][nf][2] + b0, acc[mf][nf][3] + b1);
            } else {
                *(float2*)&C[(size_t)r * DD + c] =
                    make_float2(acc[mf][nf][0] + b0, acc[mf][nf][1] + b1);
                *(float2*)&C[(size_t)(r + 8) * DD + c] =
                    make_float2(acc[mf][nf][2] + b0, acc[mf][nf][3] + b1);
            }
        }
    }
}

struct ProjArgs {
    const __half* A[3];
    const __half* W[3];
    const float* bias[3];
    __half* C[3];
};

__global__ __launch_bounds__(256, 2) void gemm_proj(ProjArgs args) {
    extern __shared__ __align__(128) char smem[];
    const int z = blockIdx.z;
    gemm_body<__half>(args.A[z], args.W[z], args.bias[z], args.C[z], smem);
}

__global__ __launch_bounds__(256, 2) void gemm_out(
    const __half* __restrict__ A, const __half* __restrict__ W,
    const float* __restrict__ bias, float* __restrict__ C) {
    extern __shared__ __align__(128) char smem[];
    gemm_body<float>(A, W, bias, C, smem);
}

// ---------------------------------------------------------------------------
// fp16 flash attention v3: FIXED max (no online softmax). Scores in log2
// domain are tiny (|raw dot| <~ 20 => 2^3.6), far inside fp16 range, so
// E = 2^(s + maskbias) directly; l via ones-column MMA (exp only);
// P = E * G; O += P V. No rescale, no max shuffles, no m tracking.
// ---------------------------------------------------------------------------
#define AT_ROWB 144
#define ATQ 0                       // 128*144 = 18432
#define ATK 18432                   // 2 x 64*144 = 18432
#define ATV 36864                   // 2 x 64*144 = 18432
#define ATMB 55296                  // 2048 floats = 8192
#define AT_SMEM_BYTES 63488
#define KV_BUF_B 9216

__global__ __launch_bounds__(256, 2) void attn_tc(
    const __half* __restrict__ Qp, const __half* __restrict__ Kp,
    const __half* __restrict__ Vp, const __half* __restrict__ Gh,
    const int* __restrict__ Mp, __half* __restrict__ Op)
{
    extern __shared__ __align__(16) char smc[];
    const uint32_t sb = smem_to_u32(smc);
    float* MB = (float*)(smc + ATMB);

    const int b = blockIdx.z, h = blockIdx.y;
    const int q0 = blockIdx.x * 128;
    const int t = threadIdx.x;
    const int wid = t >> 5, lane = t & 31;
    const int g = lane >> 2, tig = lane & 3;

    // ---- prologue: Q + KV(0) cp.async; mask bias by ALU ----
    {
        const int r = t >> 1, c0 = (t & 1) * 32;
        const __half* src = Qp + (size_t)(b * SS + q0 + r) * DD + h * DK + c0;
        uint32_t dst = sb + ATQ + r * AT_ROWB + c0 * 2;
        CP_ASYNC16(dst, src);
        CP_ASYNC16(dst + 16, src + 8);
        CP_ASYNC16(dst + 32, src + 16);
        CP_ASYNC16(dst + 48, src + 24);
    }
    {
        const int r = t >> 2, co = (t & 3) * 32;
        const __half* ksrc = Kp + (size_t)(b * SS + r) * DD + h * DK;
        const __half* vsrc = Vp + (size_t)(b * SS + r) * DD + h * DK;
        uint32_t kd = sb + ATK + r * AT_ROWB + co;
        uint32_t vd = sb + ATV + r * AT_ROWB + co;
        CP_ASYNC16(kd, ksrc + co / 2);
        CP_ASYNC16(kd + 16, ksrc + co / 2 + 8);
        CP_ASYNC16(vd, vsrc + co / 2);
        CP_ASYNC16(vd + 16, vsrc + co / 2 + 8);
    }
    CP_COMMIT();
    // mask -> log2-domain additive bias (0 or -1e5)
    for (int i = t; i < SS; i += 256)
        MB[i] = Mp[b * SS + i] ? 0.0f : -1e5f;

    const int rq0 = q0 + 16 * wid + g;
    const int rq1 = rq0 + 8;

    const uint32_t qoff = (uint32_t)((16 * wid + (lane & 15)) * AT_ROWB + (lane >> 4) * 16);
    const uint32_t koff = (uint32_t)(((lane & 7) + (lane >> 4) * 8) * AT_ROWB
                                     + ((lane >> 3) & 1) * 16);
    const uint32_t voff = (uint32_t)(((lane & 7) + ((lane >> 3) & 1) * 8) * AT_ROWB
                                     + (lane >> 4) * 16);
    const uint32_t bones = (g == 0) ? 0x3C003C00u : 0u;

    CP_WAIT0();
    __syncthreads();

    // hoist Q fragments (16 regs)
    uint32_t qf[4][4];
#pragma unroll
    for (int ks = 0; ks < 4; ks++) ldsm4(qf[ks], sb + ATQ + qoff + ks * 32);

    float O[9][4];
#pragma unroll
    for (int d = 0; d < 9; d++)
#pragma unroll
        for (int j = 0; j < 4; j++) O[d][j] = 0.0f;

    const __half2* G0 = (const __half2*)(Gh + ((size_t)b * SS + rq0) * SS);
    const __half2* G1 = (const __half2*)(Gh + ((size_t)b * SS + rq1) * SS);
    const float CS = 0.1803368867f;  // 0.125 * log2(e)
    const int NKT = SS / 64;         // 32

    for (int it = 0; it < NKT; it++) {
        // prefetch next K/V tile into the other buffer
        if (it + 1 < NKT) {
            const int r = t >> 2, co = (t & 3) * 32;
            const int nk = (it + 1) * 64;
            const __half* ksrc = Kp + (size_t)(b * SS + nk + r) * DD + h * DK;
            const __half* vsrc = Vp + (size_t)(b * SS + nk + r) * DD + h * DK;
            const uint32_t bf = (uint32_t)((it + 1) & 1) * KV_BUF_B;
            uint32_t kd = sb + ATK + bf + r * AT_ROWB + co;
            uint32_t vd = sb + ATV + bf + r * AT_ROWB + co;
            CP_ASYNC16(kd, ksrc + co / 2);
            CP_ASYNC16(kd + 16, ksrc + co / 2 + 8);
            CP_ASYNC16(vd, vsrc + co / 2);
            CP_ASYNC16(vd + 16, vsrc + co / 2 + 8);
            CP_COMMIT();
            CP_WAIT1();
        } else {
            CP_WAIT0();
        }
        __syncthreads();

        const int k0 = it * 64;
        const uint32_t sKb = sb + ATK + (uint32_t)(it & 1) * KV_BUF_B;
        const uint32_t sVb = sb + ATV + (uint32_t)(it & 1) * KV_BUF_B;

        // ---- S = Q K^T ----
        float S[8][4];
#pragma unroll
        for (int nf = 0; nf < 8; nf++)
#pragma unroll
            for (int j = 0; j < 4; j++) S[nf][j] = 0.0f;
#pragma unroll
        for (int ks = 0; ks < 4; ks++) {
#pragma unroll
            for (int np = 0; np < 4; np++) {
                uint32_t t4[4];
                ldsm4(t4, sKb + koff + np * (16 * AT_ROWB) + ks * 32);
                mma_f16(S[2 * np], qf[ks], t4);
                mma_f16(S[2 * np + 1], qf[ks], t4 + 2);
            }
        }

        // ---- E = 2^(s*CS + maskbias [+diag]) directly, fixed max = 0 ----
        const bool diagT = (k0 < q0 + 128) && (k0 + 64 > q0);
        uint32_t Ea[8], Eb[8];
#pragma unroll
        for (int nf = 0; nf < 8; nf++) {
            const int cb = k0 + 8 * nf + 2 * tig;
            float2 mb = *(float2*)&MB[cb];
            float b00 = mb.x, b01 = mb.y, b10 = mb.x, b11 = mb.y;
            if (diagT) {
                if (cb == rq0) b00 = 0.0f;
                if (cb + 1 == rq0) b01 = 0.0f;
                if (cb == rq1) b10 = 0.0f;
                if (cb + 1 == rq1) b11 = 0.0f;
            }
            float s0 = fmaf(S[nf][0], CS, b00);
            float s1 = fmaf(S[nf][1], CS, b01);
            float s2 = fmaf(S[nf][2], CS, b10);
            float s3 = fmaf(S[nf][3], CS, b11);
            Ea[nf] = h2ex2(packh2(s0, s1));
            Eb[nf] = h2ex2(packh2(s2, s3));
        }

        // ---- l += sum_k E via ones-column MMA (denominator = sum exp) ----
#pragma unroll
        for (int ks = 0; ks < 4; ks++) {
            uint32_t a[4] = {Ea[2 * ks], Eb[2 * ks], Ea[2 * ks + 1], Eb[2 * ks + 1]};
            uint32_t bo[2] = {bones, bones};
            mma_f16(O[8], a, bo);
        }

        // ---- P = E * G in place ----
#pragma unroll
        for (int nf = 0; nf < 8; nf++) {
            const int ci = 4 * nf + tig;
            Ea[nf] = h2mul(Ea[nf], *(const uint32_t*)&G0[(size_t)(k0 / 2) + ci]);
            Eb[nf] = h2mul(Eb[nf], *(const uint32_t*)&G1[(size_t)(k0 / 2) + ci]);
        }

        // ---- O += P V ----
#pragma unroll
        for (int ks = 0; ks < 4; ks++) {
            uint32_t a[4] = {Ea[2 * ks], Eb[2 * ks], Ea[2 * ks + 1], Eb[2 * ks + 1]};
#pragma unroll
            for (int dp = 0; dp < 4; dp++) {
                uint32_t t4[4];
                ldsm4t(t4, sVb + voff + ks * (16 * AT_ROWB) + dp * 32);
                mma_f16(O[2 * dp], a, t4);
                mma_f16(O[2 * dp + 1], a, t4 + 2);
            }
        }
        __syncthreads();
    }

    // ---- epilogue: l from ones-frag (tig==0 holds col 64), normalize ----
    const float l0 = __shfl_sync(0xffffffffu, O[8][0], lane & ~3);
    const float l1 = __shfl_sync(0xffffffffu, O[8][2], lane & ~3);
    const float inv0 = 1.0f / l0;
    const float inv1 = 1.0f / l1;
    __half* o0 = Op + (size_t)(b * SS + rq0) * DD + h * DK;
    __half* o1 = Op + (size_t)(b * SS + rq1) * DD + h * DK;
#pragma unroll
    for (int df = 0; df < 8; df++) {
        const int c = 8 * df + 2 * tig;
        *(__half2*)(o0 + c) = __floats2half2_rn(O[df][0] * inv0, O[df][1] * inv0);
        *(__half2*)(o1 + c) = __floats2half2_rn(O[df][2] * inv1, O[df][3] * inv1);
    }
}

// ---------------------------------------------------------------------------
extern "C" void kernel_launch(void* const* d_in, const int* in_sizes, int n_in,
                              void* d_out, int out_size)
{
    const float* query = (const float*)d_in[0];
    const float* key   = (const float*)d_in[1];
    const float* value = (const float*)d_in[2];
    const float* gprob = (const float*)d_in[3];
    const int*   mask  = (const int*)d_in[4];
    const float* Wq = (const float*)d_in[5];
    const float* bq = (const float*)d_in[6];
    const float* Wk = (const float*)d_in[7];
    const float* bk = (const float*)d_in[8];
    const float* Wv = (const float*)d_in[9];
    const float* bv = (const float*)d_in[10];
    const float* Wo = (const float*)d_in[11];
    const float* bo = (const float*)d_in[12];
    float* out = (float*)d_out;

    __half *in_h, *w_h, *qkv, *o_h, *gh;
    cudaGetSymbolAddress((void**)&in_h, g_in_h);
    cudaGetSymbolAddress((void**)&w_h, g_w_h);
    cudaGetSymbolAddress((void**)&qkv, g_qkv);
    cudaGetSymbolAddress((void**)&o_h, g_o_h);
    cudaGetSymbolAddress((void**)&gh, g_gh);

    cudaFuncSetAttribute(gemm_proj, cudaFuncAttributeMaxDynamicSharedMemorySize, G_SMEM_TOTAL);
    cudaFuncSetAttribute(gemm_out, cudaFuncAttributeMaxDynamicSharedMemorySize, G_SMEM_TOTAL);
    cudaFuncSetAttribute(attn_tc, cudaFuncAttributeMaxDynamicSharedMemorySize, AT_SMEM_BYTES);

    // converts: activations (z=3), weights (z=4), group_prob (z=1)
    CvtArgs ca;
    ca.src[0] = query; ca.src[1] = key; ca.src[2] = value; ca.src[3] = query;
    ca.dst[0] = in_h; ca.dst[1] = in_h + MD; ca.dst[2] = in_h + 2 * MD; ca.dst[3] = in_h;
    cvt_half<<<dim3(MD / 8 / 256, 1, 3), 256>>>(ca);

    CvtArgs cw;
    cw.src[0] = Wq; cw.src[1] = Wk; cw.src[2] = Wv; cw.src[3] = Wo;
    cw.dst[0] = w_h; cw.dst[1] = w_h + NN; cw.dst[2] = w_h + 2 * NN; cw.dst[3] = w_h + 3 * NN;
    cvt_half<<<dim3(NN / 8 / 256, 1, 4), 256>>>(cw);

    CvtArgs cg;
    cg.src[0] = gprob; cg.dst[0] = gh;
    cvt_half<<<dim3(GG / 8 / 256, 1, 1), 256>>>(cg);

    // fused Q/K/V projection
    ProjArgs pa;
    for (int i = 0; i < 3; i++) {
        pa.A[i] = in_h + (size_t)i * MD;
        pa.W[i] = w_h + (size_t)i * NN;
        pa.C[i] = qkv + (size_t)i * MD;
    }
    pa.bias[0] = bq; pa.bias[1] = bk; pa.bias[2] = bv;
    gemm_proj<<<dim3(DD / 128, MROWS / 128, 3), 256, G_SMEM_TOTAL>>>(pa);

    attn_tc<<<dim3(SS / 128, HH, BB), 256, AT_SMEM_BYTES>>>(
        qkv, qkv + MD, qkv + 2 * MD, gh, mask, o_h);

    gemm_out<<<dim3(DD / 128, MROWS / 128), 256, G_SMEM_TOTAL>>>(
        o_h, w_h + 3 * NN, bo, out);
}

// round 16
// speedup vs baseline: 1.0225x; 1.0225x over previous
#include <cuda_runtime.h>
#include <cuda_fp16.h>
#include <cstdint>

// Problem constants
#define BB 2
#define SS 2048
#define DD 1024
#define HH 16
#define DK 64
#define MROWS 4096
#define MD (MROWS * DD)
#define NN (DD * DD)

// Scratch (alloc-free rule: __device__ globals), all fp16
__device__ __half g_in_h[3 * MD];   // query,key,value converted
__device__ __half g_w_h[4 * NN];    // Wq,Wk,Wv,Wo converted
__device__ __half g_qkv[3 * MD];    // projected Q,K,V
__device__ __half g_o_h[MD];        // attention output

// ---------------------------------------------------------------------------
// Helpers
// ---------------------------------------------------------------------------
__device__ __forceinline__ uint32_t smem_to_u32(const void* p) {
    uint32_t a;
    asm("{ .reg .u64 t; cvta.to.shared.u64 t, %1; cvt.u32.u64 %0, t; }" : "=r"(a) : "l"(p));
    return a;
}
__device__ __forceinline__ uint32_t packh2(float x, float y) {
    __half2 h = __floats2half2_rn(x, y);
    return *(uint32_t*)&h;
}
__device__ __forceinline__ float fex2(float x) {
    float r; asm("ex2.approx.f32 %0, %1;" : "=f"(r) : "f"(x)); return r;
}
#define CP_ASYNC16(dst, src) \
    asm volatile("cp.async.cg.shared.global [%0], [%1], 16;" :: "r"((uint32_t)(dst)), "l"(src))
#define CP_COMMIT() asm volatile("cp.async.commit_group;" ::: "memory")
#define CP_WAIT2()  asm volatile("cp.async.wait_group 2;" ::: "memory")
#define CP_WAIT1()  asm volatile("cp.async.wait_group 1;" ::: "memory")
#define CP_WAIT0()  asm volatile("cp.async.wait_group 0;" ::: "memory")

__device__ __forceinline__ void mma_f16(float* c, const uint32_t* a, const uint32_t* b) {
    asm volatile(
        "mma.sync.aligned.m16n8k16.row.col.f32.f16.f16.f32 "
        "{%0,%1,%2,%3}, {%4,%5,%6,%7}, {%8,%9}, {%0,%1,%2,%3};"
        : "+f"(c[0]), "+f"(c[1]), "+f"(c[2]), "+f"(c[3])
        : "r"(a[0]), "r"(a[1]), "r"(a[2]), "r"(a[3]), "r"(b[0]), "r"(b[1]));
}
__device__ __forceinline__ void ldsm4(uint32_t* r, uint32_t a) {
    asm volatile("ldmatrix.sync.aligned.m8n8.x4.shared.b16 {%0,%1,%2,%3}, [%4];"
        : "=r"(r[0]), "=r"(r[1]), "=r"(r[2]), "=r"(r[3]) : "r"(a));
}
__device__ __forceinline__ void ldsm4t(uint32_t* r, uint32_t a) {
    asm volatile("ldmatrix.sync.aligned.m8n8.x4.trans.shared.b16 {%0,%1,%2,%3}, [%4];"
        : "=r"(r[0]), "=r"(r[1]), "=r"(r[2]), "=r"(r[3]) : "r"(a));
}

// ---------------------------------------------------------------------------
// Batched fp32 -> fp16 convert
// ---------------------------------------------------------------------------
struct CvtArgs { const float* src[4]; __half* dst[4]; };

__global__ __launch_bounds__(256) void cvt_half(CvtArgs args) {
    const float* in = args.src[blockIdx.z];
    __half* out = args.dst[blockIdx.z];
    int i = (blockIdx.x * 256 + threadIdx.x) * 8;
    float4 v0 = *(const float4*)(in + i);
    float4 v1 = *(const float4*)(in + i + 4);
    uint4 o;
    o.x = packh2(v0.x, v0.y);
    o.y = packh2(v0.z, v0.w);
    o.z = packh2(v1.x, v1.y);
    o.w = packh2(v1.z, v1.w);
    *(uint4*)(out + i) = o;
}

// ---------------------------------------------------------------------------
// fp16 GEMM (exact R8 config, proven): C = A * W^T + bias
// 128x128x32 tiles, 256 threads (8 warps 2x4), warp tile 64x32, ldmatrix.
// ---------------------------------------------------------------------------
#define G_NS 4
#define G_ROWB 80
#define G_TILE_B (128 * G_ROWB)
#define G_STAGE_B (2 * G_TILE_B)
#define G_SMEM_TOTAL (G_NS * G_STAGE_B)

template <typename OutT>
__device__ __forceinline__ void gemm_body(
    const __half* __restrict__ A, const __half* __restrict__ W,
    const float* __restrict__ bias, OutT* __restrict__ C, char* smem)
{
    const uint32_t sb = smem_to_u32(smem);
    const int t = threadIdx.x;
    const int wid = t >> 5, lane = t & 31;
    const int g = lane >> 2, tig = lane & 3;
    const int wm = wid >> 2, wn = wid & 3;
    const int m0 = blockIdx.y * 128, n0 = blockIdx.x * 128;
    const int K = DD;

    const __half* Ab = A + (size_t)m0 * K;
    const __half* Wb = W + (size_t)n0 * K;

    const int lrow = t >> 1;
    const int cp = (t & 1) * 2;

    auto load_stage = [&](int s, int kt) {
        uint32_t sa = sb + s * G_STAGE_B + lrow * G_ROWB + cp * 16;
        uint32_t sw = sa + G_TILE_B;
        const __half* ga = Ab + (size_t)lrow * K + kt * 32 + cp * 8;
        const __half* gw = Wb + (size_t)lrow * K + kt * 32 + cp * 8;
        CP_ASYNC16(sa, ga);
        CP_ASYNC16(sa + 16, ga + 8);
        CP_ASYNC16(sw, gw);
        CP_ASYNC16(sw + 16, gw + 8);
    };

    const uint32_t aoff = (uint32_t)((wm * 64 + (lane & 15)) * G_ROWB + (lane >> 4) * 16);
    const uint32_t boff = (uint32_t)((wn * 32 + (lane & 7) + (lane >> 4) * 8) * G_ROWB
                                     + ((lane >> 3) & 1) * 16);

    float acc[4][4][4];
#pragma unroll
    for (int i = 0; i < 4; i++)
#pragma unroll
        for (int j = 0; j < 4; j++)
#pragma unroll
            for (int k = 0; k < 4; k++) acc[i][j][k] = 0.0f;

    const int NT = K / 32;
    for (int s = 0; s < G_NS - 1; s++) { load_stage(s, s); CP_COMMIT(); }

    for (int kt = 0; kt < NT; kt++) {
        CP_WAIT2();
        __syncthreads();
        {
            const uint32_t sA = sb + (kt & 3) * G_STAGE_B;
            const uint32_t sW = sA + G_TILE_B;
#pragma unroll
            for (int ks = 0; ks < 2; ks++) {
                uint32_t a[4][4], b[4][2];
#pragma unroll
                for (int mf = 0; mf < 4; mf++)
                    ldsm4(a[mf], sA + aoff + mf * (16 * G_ROWB) + ks * 32);
#pragma unroll
                for (int np = 0; np < 2; np++) {
                    uint32_t t4[4];
                    ldsm4(t4, sW + boff + np * (16 * G_ROWB) + ks * 32);
                    b[2 * np][0] = t4[0]; b[2 * np][1] = t4[1];
                    b[2 * np + 1][0] = t4[2]; b[2 * np + 1][1] = t4[3];
                }
#pragma unroll
                for (int mf = 0; mf < 4; mf++)
#pragma unroll
                    for (int nf = 0; nf < 4; nf++)
                        mma_f16(acc[mf][nf], a[mf], b[nf]);
            }
        }
        __syncthreads();
        const int nx = kt + G_NS - 1;
        if (nx < NT) { load_stage(nx & 3, nx); CP_COMMIT(); }
    }

#pragma unroll
    for (int mf = 0; mf < 4; mf++) {
        const int r = m0 + wm * 64 + mf * 16 + g;
#pragma unroll
        for (int nf = 0; nf < 4; nf++) {
            const int c = n0 + wn * 32 + nf * 8 + tig * 2;
            const float b0 = bias[c], b1 = bias[c + 1];
            if constexpr (sizeof(OutT) == 2) {
                __half2* p0 = (__half2*)&C[(size_t)r * DD + c];
                __half2* p1 = (__half2*)&C[(size_t)(r + 8) * DD + c];
                *p0 = __floats2half2_rn(acc[mf][nf][0] + b0, acc[mf][nf][1] + b1);
                *p1 = __floats2half2_rn(acc[mf][nf][2] + b0, acc[mf][nf][3] + b1);
            } else {
                *(float2*)&C[(size_t)r * DD + c] =
                    make_float2(acc[mf][nf][0] + b0, acc[mf][nf][1] + b1);
                *(float2*)&C[(size_t)(r + 8) * DD + c] =
                    make_float2(acc[mf][nf][2] + b0, acc[mf][nf][3] + b1);
            }
        }
    }
}

struct ProjArgs {
    const __half* A[3];
    const __half* W[3];
    const float* bias[3];
    __half* C[3];
};

__global__ __launch_bounds__(256, 2) void gemm_proj(ProjArgs args) {
    extern __shared__ __align__(128) char smem[];
    const int z = blockIdx.z;
    gemm_body<__half>(args.A[z], args.W[z], args.bias[z], args.C[z], smem);
}

__global__ __launch_bounds__(256, 2) void gemm_out(
    const __half* __restrict__ A, const __half* __restrict__ W,
    const float* __restrict__ bias, float* __restrict__ C) {
    extern __shared__ __align__(128) char smem[];
    gemm_body<float>(A, W, bias, C, smem);
}

// ---------------------------------------------------------------------------
// fp16 flash attention v4: fixed-max softmax; exp in fp32; G loaded fp32;
// P = round_fp16(exp_f32 * G_f32)  (single rounding);
// l accumulated in exact fp32 scalars (quad shuffles). PV via register-P MMA.
// ---------------------------------------------------------------------------
#define AT_ROWB 144
#define ATQ 0                       // 128*144 = 18432
#define ATK 18432                   // 2 x 64*144 = 18432
#define ATV 36864                   // 2 x 64*144 = 18432
#define ATMB 55296                  // 2048 floats = 8192
#define AT_SMEM_BYTES 63488
#define KV_BUF_B 9216

__global__ __launch_bounds__(256, 2) void attn_tc(
    const __half* __restrict__ Qp, const __half* __restrict__ Kp,
    const __half* __restrict__ Vp, const float* __restrict__ Gp,
    const int* __restrict__ Mp, __half* __restrict__ Op)
{
    extern __shared__ __align__(16) char smc[];
    const uint32_t sb = smem_to_u32(smc);
    float* MB = (float*)(smc + ATMB);

    const int b = blockIdx.z, h = blockIdx.y;
    const int q0 = blockIdx.x * 128;
    const int t = threadIdx.x;
    const int wid = t >> 5, lane = t & 31;
    const int g = lane >> 2, tig = lane & 3;

    // ---- prologue: Q + KV(0) cp.async; mask bias by ALU ----
    {
        const int r = t >> 1, c0 = (t & 1) * 32;
        const __half* src = Qp + (size_t)(b * SS + q0 + r) * DD + h * DK + c0;
        uint32_t dst = sb + ATQ + r * AT_ROWB + c0 * 2;
        CP_ASYNC16(dst, src);
        CP_ASYNC16(dst + 16, src + 8);
        CP_ASYNC16(dst + 32, src + 16);
        CP_ASYNC16(dst + 48, src + 24);
    }
    {
        const int r = t >> 2, co = (t & 3) * 32;
        const __half* ksrc = Kp + (size_t)(b * SS + r) * DD + h * DK;
        const __half* vsrc = Vp + (size_t)(b * SS + r) * DD + h * DK;
        uint32_t kd = sb + ATK + r * AT_ROWB + co;
        uint32_t vd = sb + ATV + r * AT_ROWB + co;
        CP_ASYNC16(kd, ksrc + co / 2);
        CP_ASYNC16(kd + 16, ksrc + co / 2 + 8);
        CP_ASYNC16(vd, vsrc + co / 2);
        CP_ASYNC16(vd + 16, vsrc + co / 2 + 8);
    }
    CP_COMMIT();
    for (int i = t; i < SS; i += 256)
        MB[i] = Mp[b * SS + i] ? 0.0f : -1e5f;

    const int rq0 = q0 + 16 * wid + g;
    const int rq1 = rq0 + 8;

    const uint32_t qoff = (uint32_t)((16 * wid + (lane & 15)) * AT_ROWB + (lane >> 4) * 16);
    const uint32_t koff = (uint32_t)(((lane & 7) + (lane >> 4) * 8) * AT_ROWB
                                     + ((lane >> 3) & 1) * 16);
    const uint32_t voff = (uint32_t)(((lane & 7) + ((lane >> 3) & 1) * 8) * AT_ROWB
                                     + (lane >> 4) * 16);

    CP_WAIT0();
    __syncthreads();

    uint32_t qf[4][4];
#pragma unroll
    for (int ks = 0; ks < 4; ks++) ldsm4(qf[ks], sb + ATQ + qoff + ks * 32);

    float O[8][4];
#pragma unroll
    for (int d = 0; d < 8; d++)
#pragma unroll
        for (int j = 0; j < 4; j++) O[d][j] = 0.0f;
    float l0r = 0.0f, l1r = 0.0f;

    const float2* G0 = (const float2*)(Gp + ((size_t)b * SS + rq0) * SS);
    const float2* G1 = (const float2*)(Gp + ((size_t)b * SS + rq1) * SS);
    const float CS = 0.1803368867f;  // 0.125 * log2(e)
    const int NKT = SS / 64;         // 32

    for (int it = 0; it < NKT; it++) {
        if (it + 1 < NKT) {
            const int r = t >> 2, co = (t & 3) * 32;
            const int nk = (it + 1) * 64;
            const __half* ksrc = Kp + (size_t)(b * SS + nk + r) * DD + h * DK;
            const __half* vsrc = Vp + (size_t)(b * SS + nk + r) * DD + h * DK;
            const uint32_t bf = (uint32_t)((it + 1) & 1) * KV_BUF_B;
            uint32_t kd = sb + ATK + bf + r * AT_ROWB + co;
            uint32_t vd = sb + ATV + bf + r * AT_ROWB + co;
            CP_ASYNC16(kd, ksrc + co / 2);
            CP_ASYNC16(kd + 16, ksrc + co / 2 + 8);
            CP_ASYNC16(vd, vsrc + co / 2);
            CP_ASYNC16(vd + 16, vsrc + co / 2 + 8);
            CP_COMMIT();
            CP_WAIT1();
        } else {
            CP_WAIT0();
        }
        __syncthreads();

        const int k0 = it * 64;
        const uint32_t sKb = sb + ATK + (uint32_t)(it & 1) * KV_BUF_B;
        const uint32_t sVb = sb + ATV + (uint32_t)(it & 1) * KV_BUF_B;

        // ---- S = Q K^T ----
        float S[8][4];
#pragma unroll
        for (int nf = 0; nf < 8; nf++)
#pragma unroll
            for (int j = 0; j < 4; j++) S[nf][j] = 0.0f;
#pragma unroll
        for (int ks = 0; ks < 4; ks++) {
#pragma unroll
            for (int np = 0; np < 4; np++) {
                uint32_t t4[4];
                ldsm4(t4, sKb + koff + np * (16 * AT_ROWB) + ks * 32);
                mma_f16(S[2 * np], qf[ks], t4);
                mma_f16(S[2 * np + 1], qf[ks], t4 + 2);
            }
        }

        // ---- fp32 exp (fixed max 0) + fp32 G -> single-rounded P; l in fp32 ----
        const bool diagT = (k0 < q0 + 128) && (k0 + 64 > q0);
        uint32_t Pa[8], Pb[8];
        float rs0 = 0.0f, rs1 = 0.0f;
#pragma unroll
        for (int nf = 0; nf < 8; nf++) {
            const int cb = k0 + 8 * nf + 2 * tig;
            float2 mb = *(float2*)&MB[cb];
            float b00 = mb.x, b01 = mb.y, b10 = mb.x, b11 = mb.y;
            if (diagT) {
                if (cb == rq0) b00 = 0.0f;
                if (cb + 1 == rq0) b01 = 0.0f;
                if (cb == rq1) b10 = 0.0f;
                if (cb + 1 == rq1) b11 = 0.0f;
            }
            float e0 = fex2(fmaf(S[nf][0], CS, b00));
            float e1 = fex2(fmaf(S[nf][1], CS, b01));
            float e2 = fex2(fmaf(S[nf][2], CS, b10));
            float e3 = fex2(fmaf(S[nf][3], CS, b11));
            rs0 += e0 + e1;
            rs1 += e2 + e3;
            const int ci = 4 * nf + tig;
            float2 ga = G0[(size_t)(k0 / 2) + ci];
            float2 gb = G1[(size_t)(k0 / 2) + ci];
            Pa[nf] = packh2(e0 * ga.x, e1 * ga.y);
            Pb[nf] = packh2(e2 * gb.x, e3 * gb.y);
        }
        rs0 += __shfl_xor_sync(0xffffffffu, rs0, 1);
        rs0 += __shfl_xor_sync(0xffffffffu, rs0, 2);
        rs1 += __shfl_xor_sync(0xffffffffu, rs1, 1);
        rs1 += __shfl_xor_sync(0xffffffffu, rs1, 2);
        l0r += rs0;
        l1r += rs1;

        // ---- O += P V ----
#pragma unroll
        for (int ks = 0; ks < 4; ks++) {
            uint32_t a[4] = {Pa[2 * ks], Pb[2 * ks], Pa[2 * ks + 1], Pb[2 * ks + 1]};
#pragma unroll
            for (int dp = 0; dp < 4; dp++) {
                uint32_t t4[4];
                ldsm4t(t4, sVb + voff + ks * (16 * AT_ROWB) + dp * 32);
                mma_f16(O[2 * dp], a, t4);
                mma_f16(O[2 * dp + 1], a, t4 + 2);
            }
        }
        __syncthreads();
    }

    // ---- epilogue: normalize by exact fp32 l, store half ----
    const float inv0 = 1.0f / l0r;
    const float inv1 = 1.0f / l1r;
    __half* o0 = Op + (size_t)(b * SS + rq0) * DD + h * DK;
    __half* o1 = Op + (size_t)(b * SS + rq1) * DD + h * DK;
#pragma unroll
    for (int df = 0; df < 8; df++) {
        const int c = 8 * df + 2 * tig;
        *(__half2*)(o0 + c) = __floats2half2_rn(O[df][0] * inv0, O[df][1] * inv0);
        *(__half2*)(o1 + c) = __floats2half2_rn(O[df][2] * inv1, O[df][3] * inv1);
    }
}

// ---------------------------------------------------------------------------
extern "C" void kernel_launch(void* const* d_in, const int* in_sizes, int n_in,
                              void* d_out, int out_size)
{
    const float* query = (const float*)d_in[0];
    const float* key   = (const float*)d_in[1];
    const float* value = (const float*)d_in[2];
    const float* gprob = (const float*)d_in[3];
    const int*   mask  = (const int*)d_in[4];
    const float* Wq = (const float*)d_in[5];
    const float* bq = (const float*)d_in[6];
    const float* Wk = (const float*)d_in[7];
    const float* bk = (const float*)d_in[8];
    const float* Wv = (const float*)d_in[9];
    const float* bv = (const float*)d_in[10];
    const float* Wo = (const float*)d_in[11];
    const float* bo = (const float*)d_in[12];
    float* out = (float*)d_out;

    __half *in_h, *w_h, *qkv, *o_h;
    cudaGetSymbolAddress((void**)&in_h, g_in_h);
    cudaGetSymbolAddress((void**)&w_h, g_w_h);
    cudaGetSymbolAddress((void**)&qkv, g_qkv);
    cudaGetSymbolAddress((void**)&o_h, g_o_h);

    cudaFuncSetAttribute(gemm_proj, cudaFuncAttributeMaxDynamicSharedMemorySize, G_SMEM_TOTAL);
    cudaFuncSetAttribute(gemm_out, cudaFuncAttributeMaxDynamicSharedMemorySize, G_SMEM_TOTAL);
    cudaFuncSetAttribute(attn_tc, cudaFuncAttributeMaxDynamicSharedMemorySize, AT_SMEM_BYTES);

    // converts: activations (z=3), weights (z=4). group_prob stays fp32.
    CvtArgs ca;
    ca.src[0] = query; ca.src[1] = key; ca.src[2] = value; ca.src[3] = query;
    ca.dst[0] = in_h; ca.dst[1] = in_h + MD; ca.dst[2] = in_h + 2 * MD; ca.dst[3] = in_h;
    cvt_half<<<dim3(MD / 8 / 256, 1, 3), 256>>>(ca);

    CvtArgs cw;
    cw.src[0] = Wq; cw.src[1] = Wk; cw.src[2] = Wv; cw.src[3] = Wo;
    cw.dst[0] = w_h; cw.dst[1] = w_h + NN; cw.dst[2] = w_h + 2 * NN; cw.dst[3] = w_h + 3 * NN;
    cvt_half<<<dim3(NN / 8 / 256, 1, 4), 256>>>(cw);

    // fused Q/K/V projection (proven 128x128 tiles)
    ProjArgs pa;
    for (int i = 0; i < 3; i++) {
        pa.A[i] = in_h + (size_t)i * MD;
        pa.W[i] = w_h + (size_t)i * NN;
        pa.C[i] = qkv + (size_t)i * MD;
    }
    pa.bias[0] = bq; pa.bias[1] = bk; pa.bias[2] = bv;
    gemm_proj<<<dim3(DD / 128, MROWS / 128, 3), 256, G_SMEM_TOTAL>>>(pa);

    attn_tc<<<dim3(SS / 128, HH, BB), 256, AT_SMEM_BYTES>>>(
        qkv, qkv + MD, qkv + 2 * MD, gprob, mask, o_h);

    gemm_out<<<dim3(DD / 128, MROWS / 128), 256, G_SMEM_TOTAL>>>(
        o_h, w_h + 3 * NN, bo, out);
}

// round 17
// speedup vs baseline: 1.0962x; 1.0720x over previous
#include <cuda_runtime.h>
#include <cuda_fp16.h>
#include <cstdint>

// Problem constants
#define BB 2
#define SS 2048
#define DD 1024
#define HH 16
#define DK 64
#define MROWS 4096
#define MD (MROWS * DD)
#define NN (DD * DD)

// Scratch (alloc-free rule: __device__ globals), all fp16
__device__ __half g_in_h[3 * MD];   // query,key,value converted
__device__ __half g_w_h[4 * NN];    // Wq,Wk,Wv,Wo converted
__device__ __half g_qkv[3 * MD];    // projected Q,K,V
__device__ __half g_o_h[MD];        // attention output

// ---------------------------------------------------------------------------
// Helpers
// ---------------------------------------------------------------------------
__device__ __forceinline__ uint32_t smem_to_u32(const void* p) {
    uint32_t a;
    asm("{ .reg .u64 t; cvta.to.shared.u64 t, %1; cvt.u32.u64 %0, t; }" : "=r"(a) : "l"(p));
    return a;
}
__device__ __forceinline__ uint32_t packh2(float x, float y) {
    __half2 h = __floats2half2_rn(x, y);
    return *(uint32_t*)&h;
}
__device__ __forceinline__ float fex2(float x) {
    float r; asm("ex2.approx.f32 %0, %1;" : "=f"(r) : "f"(x)); return r;
}
#define CP_ASYNC16(dst, src) \
    asm volatile("cp.async.cg.shared.global [%0], [%1], 16;" :: "r"((uint32_t)(dst)), "l"(src))
#define CP_COMMIT() asm volatile("cp.async.commit_group;" ::: "memory")
#define CP_WAIT2()  asm volatile("cp.async.wait_group 2;" ::: "memory")
#define CP_WAIT1()  asm volatile("cp.async.wait_group 1;" ::: "memory")
#define CP_WAIT0()  asm volatile("cp.async.wait_group 0;" ::: "memory")

__device__ __forceinline__ void mma_f16(float* c, const uint32_t* a, const uint32_t* b) {
    asm volatile(
        "mma.sync.aligned.m16n8k16.row.col.f32.f16.f16.f32 "
        "{%0,%1,%2,%3}, {%4,%5,%6,%7}, {%8,%9}, {%0,%1,%2,%3};"
        : "+f"(c[0]), "+f"(c[1]), "+f"(c[2]), "+f"(c[3])
        : "r"(a[0]), "r"(a[1]), "r"(a[2]), "r"(a[3]), "r"(b[0]), "r"(b[1]));
}
__device__ __forceinline__ void ldsm4(uint32_t* r, uint32_t a) {
    asm volatile("ldmatrix.sync.aligned.m8n8.x4.shared.b16 {%0,%1,%2,%3}, [%4];"
        : "=r"(r[0]), "=r"(r[1]), "=r"(r[2]), "=r"(r[3]) : "r"(a));
}
__device__ __forceinline__ void ldsm4t(uint32_t* r, uint32_t a) {
    asm volatile("ldmatrix.sync.aligned.m8n8.x4.trans.shared.b16 {%0,%1,%2,%3}, [%4];"
        : "=r"(r[0]), "=r"(r[1]), "=r"(r[2]), "=r"(r[3]) : "r"(a));
}

// ---------------------------------------------------------------------------
// Batched fp32 -> fp16 convert
// ---------------------------------------------------------------------------
struct CvtArgs { const float* src[4]; __half* dst[4]; };

__global__ __launch_bounds__(256) void cvt_half(CvtArgs args) {
    const float* in = args.src[blockIdx.z];
    __half* out = args.dst[blockIdx.z];
    int i = (blockIdx.x * 256 + threadIdx.x) * 8;
    float4 v0 = *(const float4*)(in + i);
    float4 v1 = *(const float4*)(in + i + 4);
    uint4 o;
    o.x = packh2(v0.x, v0.y);
    o.y = packh2(v0.z, v0.w);
    o.z = packh2(v1.x, v1.y);
    o.w = packh2(v1.z, v1.w);
    *(uint4*)(out + i) = o;
}

// ---------------------------------------------------------------------------
// fp16 GEMM: proven 128x128x32 fragment maps, NEW single-barrier loop with
// early prefetch (copies in flight during MMAs; empty commits keep the
// wait_group accounting exact on tail iterations).
// ---------------------------------------------------------------------------
#define G_NS 4
#define G_ROWB 80
#define G_TILE_B (128 * G_ROWB)
#define G_STAGE_B (2 * G_TILE_B)
#define G_SMEM_TOTAL (G_NS * G_STAGE_B)

template <typename OutT>
__device__ __forceinline__ void gemm_body(
    const __half* __restrict__ A, const __half* __restrict__ W,
    const float* __restrict__ bias, OutT* __restrict__ C, char* smem)
{
    const uint32_t sb = smem_to_u32(smem);
    const int t = threadIdx.x;
    const int wid = t >> 5, lane = t & 31;
    const int g = lane >> 2, tig = lane & 3;
    const int wm = wid >> 2, wn = wid & 3;
    const int m0 = blockIdx.y * 128, n0 = blockIdx.x * 128;
    const int K = DD;

    const __half* Ab = A + (size_t)m0 * K;
    const __half* Wb = W + (size_t)n0 * K;

    const int lrow = t >> 1;
    const int cp = (t & 1) * 2;

    auto load_stage = [&](int s, int kt) {
        uint32_t sa = sb + s * G_STAGE_B + lrow * G_ROWB + cp * 16;
        uint32_t sw = sa + G_TILE_B;
        const __half* ga = Ab + (size_t)lrow * K + kt * 32 + cp * 8;
        const __half* gw = Wb + (size_t)lrow * K + kt * 32 + cp * 8;
        CP_ASYNC16(sa, ga);
        CP_ASYNC16(sa + 16, ga + 8);
        CP_ASYNC16(sw, gw);
        CP_ASYNC16(sw + 16, gw + 8);
    };

    const uint32_t aoff = (uint32_t)((wm * 64 + (lane & 15)) * G_ROWB + (lane >> 4) * 16);
    const uint32_t boff = (uint32_t)((wn * 32 + (lane & 7) + (lane >> 4) * 8) * G_ROWB
                                     + ((lane >> 3) & 1) * 16);

    float acc[4][4][4];
#pragma unroll
    for (int i = 0; i < 4; i++)
#pragma unroll
        for (int j = 0; j < 4; j++)
#pragma unroll
            for (int k = 0; k < 4; k++) acc[i][j][k] = 0.0f;

    const int NT = K / 32;
    for (int s = 0; s < G_NS - 1; s++) { load_stage(s, s); CP_COMMIT(); }

    for (int kt = 0; kt < NT; kt++) {
        CP_WAIT2();
        __syncthreads();
        // early prefetch: stage kt+3 targets buffer (kt-1)&3, whose readers
        // (iteration kt-1) are closed by the barrier above.
        const int nx = kt + G_NS - 1;
        if (nx < NT) load_stage(nx & 3, nx);
        CP_COMMIT();   // empty group on tail iterations keeps wait counts exact
        {
            const uint32_t sA = sb + (kt & 3) * G_STAGE_B;
            const uint32_t sW = sA + G_TILE_B;
#pragma unroll
            for (int ks = 0; ks < 2; ks++) {
                uint32_t a[4][4], b[4][2];
#pragma unroll
                for (int mf = 0; mf < 4; mf++)
                    ldsm4(a[mf], sA + aoff + mf * (16 * G_ROWB) + ks * 32);
#pragma unroll
                for (int np = 0; np < 2; np++) {
                    uint32_t t4[4];
                    ldsm4(t4, sW + boff + np * (16 * G_ROWB) + ks * 32);
                    b[2 * np][0] = t4[0]; b[2 * np][1] = t4[1];
                    b[2 * np + 1][0] = t4[2]; b[2 * np + 1][1] = t4[3];
                }
#pragma unroll
                for (int mf = 0; mf < 4; mf++)
#pragma unroll
                    for (int nf = 0; nf < 4; nf++)
                        mma_f16(acc[mf][nf], a[mf], b[nf]);
            }
        }
    }

#pragma unroll
    for (int mf = 0; mf < 4; mf++) {
        const int r = m0 + wm * 64 + mf * 16 + g;
#pragma unroll
        for (int nf = 0; nf < 4; nf++) {
            const int c = n0 + wn * 32 + nf * 8 + tig * 2;
            const float b0 = bias[c], b1 = bias[c + 1];
            if constexpr (sizeof(OutT) == 2) {
                __half2* p0 = (__half2*)&C[(size_t)r * DD + c];
                __half2* p1 = (__half2*)&C[(size_t)(r + 8) * DD + c];
                *p0 = __floats2half2_rn(acc[mf][nf][0] + b0, acc[mf][nf][1] + b1);
                *p1 = __floats2half2_rn(acc[mf][nf][2] + b0, acc[mf][nf][3] + b1);
            } else {
                *(float2*)&C[(size_t)r * DD + c] =
                    make_float2(acc[mf][nf][0] + b0, acc[mf][nf][1] + b1);
                *(float2*)&C[(size_t)(r + 8) * DD + c] =
                    make_float2(acc[mf][nf][2] + b0, acc[mf][nf][3] + b1);
            }
        }
    }
}

struct ProjArgs {
    const __half* A[3];
    const __half* W[3];
    const float* bias[3];
    __half* C[3];
};

__global__ __launch_bounds__(256, 2) void gemm_proj(ProjArgs args) {
    extern __shared__ __align__(128) char smem[];
    const int z = blockIdx.z;
    gemm_body<__half>(args.A[z], args.W[z], args.bias[z], args.C[z], smem);
}

__global__ __launch_bounds__(256, 2) void gemm_out(
    const __half* __restrict__ A, const __half* __restrict__ W,
    const float* __restrict__ bias, float* __restrict__ C) {
    extern __shared__ __align__(128) char smem[];
    gemm_body<float>(A, W, bias, C, smem);
}

// ---------------------------------------------------------------------------
// fp16 flash attention v4.1: same arithmetic as v4 (fp32 exp, fp32 G,
// single-rounded P, fp32 l), NEW triple-buffered K/V + single-barrier loop
// with early prefetch.
// ---------------------------------------------------------------------------
#define AT_ROWB 144
#define KV_BUF_B 9216               // 64 * 144
#define ATQ 0                       // 128*144 = 18432
#define ATK 18432                   // 3 x 9216 = 27648
#define ATV 46080                   // 3 x 9216 = 27648
#define ATMB 73728                  // 2048 floats = 8192
#define AT_SMEM_BYTES 81920

__global__ __launch_bounds__(256, 2) void attn_tc(
    const __half* __restrict__ Qp, const __half* __restrict__ Kp,
    const __half* __restrict__ Vp, const float* __restrict__ Gp,
    const int* __restrict__ Mp, __half* __restrict__ Op)
{
    extern __shared__ __align__(16) char smc[];
    const uint32_t sb = smem_to_u32(smc);
    float* MB = (float*)(smc + ATMB);

    const int b = blockIdx.z, h = blockIdx.y;
    const int q0 = blockIdx.x * 128;
    const int t = threadIdx.x;
    const int wid = t >> 5, lane = t & 31;
    const int g = lane >> 2, tig = lane & 3;

    // KV tile loader into ring buffer slot s (0..2)
    const int kvr = t >> 2, kvc = (t & 3) * 32;
    auto load_kv = [&](int s, int tile) {
        const int k0 = tile * 64;
        const __half* ksrc = Kp + (size_t)(b * SS + k0 + kvr) * DD + h * DK;
        const __half* vsrc = Vp + (size_t)(b * SS + k0 + kvr) * DD + h * DK;
        uint32_t kd = sb + ATK + (uint32_t)s * KV_BUF_B + kvr * AT_ROWB + kvc;
        uint32_t vd = sb + ATV + (uint32_t)s * KV_BUF_B + kvr * AT_ROWB + kvc;
        CP_ASYNC16(kd, ksrc + kvc / 2);
        CP_ASYNC16(kd + 16, ksrc + kvc / 2 + 8);
        CP_ASYNC16(vd, vsrc + kvc / 2);
        CP_ASYNC16(vd + 16, vsrc + kvc / 2 + 8);
    };

    // ---- prologue: Q + tile0 (group 0), tile1 (group 1); mask bias by ALU ----
    {
        const int r = t >> 1, c0 = (t & 1) * 32;
        const __half* src = Qp + (size_t)(b * SS + q0 + r) * DD + h * DK + c0;
        uint32_t dst = sb + ATQ + r * AT_ROWB + c0 * 2;
        CP_ASYNC16(dst, src);
        CP_ASYNC16(dst + 16, src + 8);
        CP_ASYNC16(dst + 32, src + 16);
        CP_ASYNC16(dst + 48, src + 24);
    }
    load_kv(0, 0);
    CP_COMMIT();
    load_kv(1, 1);
    CP_COMMIT();
    for (int i = t; i < SS; i += 256)
        MB[i] = Mp[b * SS + i] ? 0.0f : -1e5f;

    const int rq0 = q0 + 16 * wid + g;
    const int rq1 = rq0 + 8;

    const uint32_t qoff = (uint32_t)((16 * wid + (lane & 15)) * AT_ROWB + (lane >> 4) * 16);
    const uint32_t koff = (uint32_t)(((lane & 7) + (lane >> 4) * 8) * AT_ROWB
                                     + ((lane >> 3) & 1) * 16);
    const uint32_t voff = (uint32_t)(((lane & 7) + ((lane >> 3) & 1) * 8) * AT_ROWB
                                     + (lane >> 4) * 16);

    CP_WAIT1();      // group0 (Q + tile0) complete
    __syncthreads();

    uint32_t qf[4][4];
#pragma unroll
    for (int ks = 0; ks < 4; ks++) ldsm4(qf[ks], sb + ATQ + qoff + ks * 32);

    float O[8][4];
#pragma unroll
    for (int d = 0; d < 8; d++)
#pragma unroll
        for (int j = 0; j < 4; j++) O[d][j] = 0.0f;
    float l0r = 0.0f, l1r = 0.0f;

    const float2* G0 = (const float2*)(Gp + ((size_t)b * SS + rq0) * SS);
    const float2* G1 = (const float2*)(Gp + ((size_t)b * SS + rq1) * SS);
    const float CS = 0.1803368867f;  // 0.125 * log2(e)
    const int NKT = SS / 64;         // 32

    int cur = 0, pf = 2;             // ring indices: it%3, (it+2)%3
    for (int it = 0; it < NKT; it++) {
        CP_WAIT1();      // tile `it` complete (pending: tile it+1)
        __syncthreads(); // visibility + closes readers of buffer pf (it-1's reads)
        // early prefetch tile it+2 into slot pf; readers were at it-2, closed.
        if (it + 2 < NKT) load_kv(pf, it + 2);
        CP_COMMIT();     // empty group on tail keeps wait counts exact

        const int k0 = it * 64;
        const uint32_t sKb = sb + ATK + (uint32_t)cur * KV_BUF_B;
        const uint32_t sVb = sb + ATV + (uint32_t)cur * KV_BUF_B;

        // ---- S = Q K^T ----
        float S[8][4];
#pragma unroll
        for (int nf = 0; nf < 8; nf++)
#pragma unroll
            for (int j = 0; j < 4; j++) S[nf][j] = 0.0f;
#pragma unroll
        for (int ks = 0; ks < 4; ks++) {
#pragma unroll
            for (int np = 0; np < 4; np++) {
                uint32_t t4[4];
                ldsm4(t4, sKb + koff + np * (16 * AT_ROWB) + ks * 32);
                mma_f16(S[2 * np], qf[ks], t4);
                mma_f16(S[2 * np + 1], qf[ks], t4 + 2);
            }
        }

        // ---- fp32 exp (fixed max 0) + fp32 G -> single-rounded P; l in fp32 ----
        const bool diagT = (k0 < q0 + 128) && (k0 + 64 > q0);
        uint32_t Pa[8], Pb[8];
        float rs0 = 0.0f, rs1 = 0.0f;
#pragma unroll
        for (int nf = 0; nf < 8; nf++) {
            const int cb = k0 + 8 * nf + 2 * tig;
            float2 mb = *(float2*)&MB[cb];
            float b00 = mb.x, b01 = mb.y, b10 = mb.x, b11 = mb.y;
            if (diagT) {
                if (cb == rq0) b00 = 0.0f;
                if (cb + 1 == rq0) b01 = 0.0f;
                if (cb == rq1) b10 = 0.0f;
                if (cb + 1 == rq1) b11 = 0.0f;
            }
            float e0 = fex2(fmaf(S[nf][0], CS, b00));
            float e1 = fex2(fmaf(S[nf][1], CS, b01));
            float e2 = fex2(fmaf(S[nf][2], CS, b10));
            float e3 = fex2(fmaf(S[nf][3], CS, b11));
            rs0 += e0 + e1;
            rs1 += e2 + e3;
            const int ci = 4 * nf + tig;
            float2 ga = G0[(size_t)(k0 / 2) + ci];
            float2 gb = G1[(size_t)(k0 / 2) + ci];
            Pa[nf] = packh2(e0 * ga.x, e1 * ga.y);
            Pb[nf] = packh2(e2 * gb.x, e3 * gb.y);
        }
        rs0 += __shfl_xor_sync(0xffffffffu, rs0, 1);
        rs0 += __shfl_xor_sync(0xffffffffu, rs0, 2);
        rs1 += __shfl_xor_sync(0xffffffffu, rs1, 1);
        rs1 += __shfl_xor_sync(0xffffffffu, rs1, 2);
        l0r += rs0;
        l1r += rs1;

        // ---- O += P V ----
#pragma unroll
        for (int ks = 0; ks < 4; ks++) {
            uint32_t a[4] = {Pa[2 * ks], Pb[2 * ks], Pa[2 * ks + 1], Pb[2 * ks + 1]};
#pragma unroll
            for (int dp = 0; dp < 4; dp++) {
                uint32_t t4[4];
                ldsm4t(t4, sVb + voff + ks * (16 * AT_ROWB) + dp * 32);
                mma_f16(O[2 * dp], a, t4);
                mma_f16(O[2 * dp + 1], a, t4 + 2);
            }
        }

        cur = (cur == 2) ? 0 : cur + 1;
        pf = (pf == 2) ? 0 : pf + 1;
    }

    // ---- epilogue: normalize by exact fp32 l, store half ----
    const float inv0 = 1.0f / l0r;
    const float inv1 = 1.0f / l1r;
    __half* o0 = Op + (size_t)(b * SS + rq0) * DD + h * DK;
    __half* o1 = Op + (size_t)(b * SS + rq1) * DD + h * DK;
#pragma unroll
    for (int df = 0; df < 8; df++) {
        const int c = 8 * df + 2 * tig;
        *(__half2*)(o0 + c) = __floats2half2_rn(O[df][0] * inv0, O[df][1] * inv0);
        *(__half2*)(o1 + c) = __floats2half2_rn(O[df][2] * inv1, O[df][3] * inv1);
    }
}

// ---------------------------------------------------------------------------
extern "C" void kernel_launch(void* const* d_in, const int* in_sizes, int n_in,
                              void* d_out, int out_size)
{
    const float* query = (const float*)d_in[0];
    const float* key   = (const float*)d_in[1];
    const float* value = (const float*)d_in[2];
    const float* gprob = (const float*)d_in[3];
    const int*   mask  = (const int*)d_in[4];
    const float* Wq = (const float*)d_in[5];
    const float* bq = (const float*)d_in[6];
    const float* Wk = (const float*)d_in[7];
    const float* bk = (const float*)d_in[8];
    const float* Wv = (const float*)d_in[9];
    const float* bv = (const float*)d_in[10];
    const float* Wo = (const float*)d_in[11];
    const float* bo = (const float*)d_in[12];
    float* out = (float*)d_out;

    __half *in_h, *w_h, *qkv, *o_h;
    cudaGetSymbolAddress((void**)&in_h, g_in_h);
    cudaGetSymbolAddress((void**)&w_h, g_w_h);
    cudaGetSymbolAddress((void**)&qkv, g_qkv);
    cudaGetSymbolAddress((void**)&o_h, g_o_h);

    cudaFuncSetAttribute(gemm_proj, cudaFuncAttributeMaxDynamicSharedMemorySize, G_SMEM_TOTAL);
    cudaFuncSetAttribute(gemm_out, cudaFuncAttributeMaxDynamicSharedMemorySize, G_SMEM_TOTAL);
    cudaFuncSetAttribute(attn_tc, cudaFuncAttributeMaxDynamicSharedMemorySize, AT_SMEM_BYTES);

    // converts: activations (z=3), weights (z=4). group_prob stays fp32.
    CvtArgs ca;
    ca.src[0] = query; ca.src[1] = key; ca.src[2] = value; ca.src[3] = query;
    ca.dst[0] = in_h; ca.dst[1] = in_h + MD; ca.dst[2] = in_h + 2 * MD; ca.dst[3] = in_h;
    cvt_half<<<dim3(MD / 8 / 256, 1, 3), 256>>>(ca);

    CvtArgs cw;
    cw.src[0] = Wq; cw.src[1] = Wk; cw.src[2] = Wv; cw.src[3] = Wo;
    cw.dst[0] = w_h; cw.dst[1] = w_h + NN; cw.dst[2] = w_h + 2 * NN; cw.dst[3] = w_h + 3 * NN;
    cvt_half<<<dim3(NN / 8 / 256, 1, 4), 256>>>(cw);

    // fused Q/K/V projection (proven 128x128 tiles)
    ProjArgs pa;
    for (int i = 0; i < 3; i++) {
        pa.A[i] = in_h + (size_t)i * MD;
        pa.W[i] = w_h + (size_t)i * NN;
        pa.C[i] = qkv + (size_t)i * MD;
    }
    pa.bias[0] = bq; pa.bias[1] = bk; pa.bias[2] = bv;
    gemm_proj<<<dim3(DD / 128, MROWS / 128, 3), 256, G_SMEM_TOTAL>>>(pa);

    attn_tc<<<dim3(SS / 128, HH, BB), 256, AT_SMEM_BYTES>>>(
        qkv, qkv + MD, qkv + 2 * MD, gprob, mask, o_h);

    gemm_out<<<dim3(DD / 128, MROWS / 128), 256, G_SMEM_TOTAL>>>(
        o_h, w_h + 3 * NN, bo, out);
}